// round 1
// baseline (speedup 1.0000x reference)
#include <cuda_runtime.h>
#include <math.h>

#define BS   8
#define CCH  256
#define NND  9216     // H*W
#define EED  9215     // N-1 edges
#define ZETA 0.01f
#define SPLIT 4
#define CPS  (CCH/SPLIT)   // 64 channels per split
#define MAXD 511

// scratch (static device globals — no allocations)
__device__ float g_part[(size_t)BS * SPLIT * EED];
__device__ float g_wgt[(size_t)BS * EED];

// ---------------------------------------------------------------------------
// K1: partial squared distances per edge, channel-split 4 ways for parallelism
// ---------------------------------------------------------------------------
__global__ void dist_kernel(const float* __restrict__ emb,
                            const int*   __restrict__ tree) {
    const int EB = (EED + 255) / 256;           // edge blocks per (b,g)
    int bg = blockIdx.x / EB;
    int eb = blockIdx.x % EB;
    int b  = bg / SPLIT, g = bg % SPLIT;
    int e  = eb * 256 + threadIdx.x;
    if (e >= EED) return;

    const int* tr = tree + (size_t)b * EED * 2 + (size_t)e * 2;
    int s = tr[0];
    int t = tr[1];
    const float* p = emb + ((size_t)b * CCH + (size_t)g * CPS) * NND;

    float acc = 0.f;
#pragma unroll 8
    for (int c = 0; c < CPS; c++) {
        float a  = p[(size_t)c * NND + s];
        float bb = p[(size_t)c * NND + t];
        float d  = a - bb;
        acc += d * d;
    }
    g_part[((size_t)b * SPLIT + g) * EED + e] = acc;
}

// ---------------------------------------------------------------------------
// K2: reduce partials + exp
// ---------------------------------------------------------------------------
__global__ void exp_kernel() {
    int idx = blockIdx.x * blockDim.x + threadIdx.x;
    if (idx >= BS * EED) return;
    int b = idx / EED, e = idx % EED;
    float s = 0.f;
#pragma unroll
    for (int g = 0; g < SPLIT; g++)
        s += g_part[((size_t)b * SPLIT + g) * EED + e];
    g_wgt[idx] = expf(-ZETA * s);
}

// ---------------------------------------------------------------------------
// K3: per-batch level-parallel tree scans entirely in shared memory.
// One 1024-thread block per batch. 5 regions of N ints/floats (180 KB):
//  phase A (depth):  R0=jumpA R1=jumpB R2=dA R3=dB R4=parent->depth
//  phase B (scan):   R0=S     R1=Z     R2=w  R3=order R4=depth
// ---------------------------------------------------------------------------
extern __shared__ char smem_raw[];

__global__ void __launch_bounds__(1024, 1)
scan_kernel(const float* __restrict__ fin,
            const int*   __restrict__ tree,
            float*       __restrict__ out) {
    const int b   = blockIdx.x;
    const int tid = threadIdx.x;
    const int nt  = 1024;

    int* R0 = (int*)smem_raw;
    int* R1 = R0 + NND;
    int* R2 = R1 + NND;
    int* R3 = R2 + NND;
    int* R4 = R3 + NND;   // parent, then depth

    float* S     = (float*)R0;
    float* Z     = (float*)R1;
    float* wsh   = (float*)R2;
    int*   order = R3;
    int*   dep   = R4;

    __shared__ int hist[MAXD + 1];
    __shared__ int lvl_off[MAXD + 2];
    __shared__ int s_maxLvl;

    const int* tr = tree + (size_t)b * EED * 2;

    // ---- build parent[] into R4 ----
    if (tid == 0) dep[0] = 0;
    for (int e = tid; e < EED; e += nt)
        dep[tr[2 * e + 1]] = tr[2 * e];
    __syncthreads();

    // ---- depth via pointer doubling (10 rounds -> depth <= 1024) ----
    int *jA = R0, *jB = R1, *dA = R2, *dB = R3;
    for (int i = tid; i < NND; i += nt) {
        jA[i] = dep[i];              // parent (dep[0]=0)
        dA[i] = (i == 0) ? 0 : 1;
    }
    __syncthreads();
#pragma unroll 1
    for (int r = 0; r < 10; r++) {
        for (int i = tid; i < NND; i += nt) {
            int jj = jA[i];
            dB[i] = dA[i] + dA[jj];
            jB[i] = jA[jj];
        }
        __syncthreads();
        int* tmp;
        tmp = jA; jA = jB; jB = tmp;
        tmp = dA; dA = dB; dB = tmp;
    }
    // final depths are in dA (== R2 after even #swaps); persist into R4
    for (int i = tid; i < NND; i += nt) dep[i] = dA[i];
    __syncthreads();

    // ---- counting sort of edges by child depth ----
    for (int k = tid; k <= MAXD; k += nt) hist[k] = 0;
    __syncthreads();
    for (int e = tid; e < EED; e += nt) {
        int d = dep[tr[2 * e + 1]];
        d = d > MAXD ? MAXD : d;
        atomicAdd(&hist[d], 1);
    }
    __syncthreads();
    if (tid == 0) {
        int run = 0, mx = 1;
        for (int k = 0; k <= MAXD; k++) {
            lvl_off[k] = run;
            run += hist[k];
            if (hist[k]) mx = k;
            hist[k] = lvl_off[k];   // cursor for scatter
        }
        lvl_off[MAXD + 1] = run;
        s_maxLvl = mx;
    }
    __syncthreads();
    for (int e = tid; e < EED; e += nt) {
        int d = dep[tr[2 * e + 1]];
        d = d > MAXD ? MAXD : d;
        int pos = atomicAdd(&hist[d], 1);
        order[pos] = e;
    }
    __syncthreads();

    // ---- init S (feature), Z (ones), w ----
    const float* fb = fin + (size_t)b * NND;
    for (int i = tid; i < NND; i += nt) { S[i] = fb[i]; Z[i] = 1.f; }
    for (int e = tid; e < EED; e += nt) wsh[e] = g_wgt[(size_t)b * EED + e];
    __syncthreads();

    const int maxLvl = s_maxLvl;

    // ---- UP pass: deepest level first; all children of a node share a level
    for (int d = maxLvl; d >= 1; --d) {
        int beg = lvl_off[d], end = lvl_off[d + 1];
        for (int idx = beg + tid; idx < end; idx += nt) {
            int e = order[idx];
            int s = tr[2 * e], t = tr[2 * e + 1];
            float we = wsh[e];
            atomicAdd(&S[s], we * S[t]);
            atomicAdd(&Z[s], we * Z[t]);
        }
        __syncthreads();
    }

    // ---- DOWN pass: shallowest first; writes to distinct children
    for (int d = 1; d <= maxLvl; ++d) {
        int beg = lvl_off[d], end = lvl_off[d + 1];
        for (int idx = beg + tid; idx < end; idx += nt) {
            int e = order[idx];
            int s = tr[2 * e], t = tr[2 * e + 1];
            float we = wsh[e];
            float om = 1.f - we * we;
            S[t] = we * S[s] + om * S[t];
            Z[t] = we * Z[s] + om * Z[t];
        }
        __syncthreads();
    }

    // ---- output = F/G ----
    float* ob = out + (size_t)b * NND;
    for (int i = tid; i < NND; i += nt) ob[i] = S[i] / Z[i];
}

// ---------------------------------------------------------------------------
extern "C" void kernel_launch(void* const* d_in, const int* in_sizes, int n_in,
                              void* d_out, int out_size) {
    const float* f    = (const float*)d_in[0];   // feature_in [8,1,96,96]
    const float* emb  = (const float*)d_in[1];   // embed_in   [8,256,96,96]
    const int*   tree = (const int*)d_in[2];     // tree       [8,9215,2]
    float*       out  = (float*)d_out;           // [8,1,96,96]

    const int EB = (EED + 255) / 256;
    dist_kernel<<<BS * SPLIT * EB, 256>>>(emb, tree);
    exp_kernel<<<(BS * EED + 255) / 256, 256>>>();

    size_t smem = 5 * (size_t)NND * sizeof(int);   // 184320 B
    cudaFuncSetAttribute(scan_kernel,
                         cudaFuncAttributeMaxDynamicSharedMemorySize,
                         (int)smem);
    scan_kernel<<<BS, 1024, smem>>>(f, tree, out);
}

// round 2
// speedup vs baseline: 1.3320x; 1.3320x over previous
#include <cuda_runtime.h>
#include <math.h>

#define BS   8
#define CCH  256
#define NND  9216     // H*W
#define EED  9215     // N-1 edges
#define ZETA 0.01f
#define TCH  4                 // channels per smem tile
#define SPLIT (CCH/TCH)        // 64 partials per edge
#define MAXD 511

// scratch (static device globals — no allocations)
__device__ float g_part[(size_t)BS * SPLIT * EED];
__device__ float g_wgt[(size_t)BS * EED];

// ---------------------------------------------------------------------------
// K1: partial squared distances. One 1024-thread block per (batch, 4-channel
// tile). The 4x9216 float tile (147 KB) is staged in shared memory so both
// the random src gather and the tgt read hit smem — no 32B-sector
// amplification in L2.
// ---------------------------------------------------------------------------
extern __shared__ float dyn_smem[];

__global__ void __launch_bounds__(1024, 1)
dist_kernel(const float* __restrict__ emb,
            const int*   __restrict__ tree) {
    float* tile = dyn_smem;                     // TCH * NND floats
    const int b = blockIdx.x / SPLIT;
    const int g = blockIdx.x % SPLIT;
    const int tid = threadIdx.x;

    const float* p = emb + ((size_t)b * CCH + (size_t)g * TCH) * NND;
    // coalesced vectorized tile load
    const float4* p4 = (const float4*)p;
    float4* t4 = (float4*)tile;
    for (int i = tid; i < TCH * NND / 4; i += 1024) t4[i] = p4[i];
    __syncthreads();

    const int2* tr2 = (const int2*)(tree + (size_t)b * EED * 2);
    float* outp = g_part + ((size_t)b * SPLIT + g) * EED;

    for (int e = tid; e < EED; e += 1024) {
        int2 st = tr2[e];
        int s = st.x, t = st.y;
        float acc = 0.f;
#pragma unroll
        for (int c = 0; c < TCH; c++) {
            float d = tile[c * NND + s] - tile[c * NND + t];
            acc += d * d;
        }
        outp[e] = acc;
    }
}

// ---------------------------------------------------------------------------
// K2: reduce partials + exp
// ---------------------------------------------------------------------------
__global__ void exp_kernel() {
    int idx = blockIdx.x * blockDim.x + threadIdx.x;
    if (idx >= BS * EED) return;
    int b = idx / EED, e = idx % EED;
    float s = 0.f;
#pragma unroll
    for (int g = 0; g < SPLIT; g++)
        s += g_part[((size_t)b * SPLIT + g) * EED + e];
    g_wgt[idx] = expf(-ZETA * s);
}

// ---------------------------------------------------------------------------
// K3: per-batch level-parallel tree scans entirely in shared memory.
// One 1024-thread block per batch. 5 regions of N ints/floats (180 KB):
//  phase A (depth):  R0=jumpA R1=jumpB R2=dA R3=dB R4=parent->depth
//  phase B (scan):   R0=S     R1=Z     R2=w  R3=order R4=depth
// ---------------------------------------------------------------------------
__global__ void __launch_bounds__(1024, 1)
scan_kernel(const float* __restrict__ fin,
            const int*   __restrict__ tree,
            float*       __restrict__ out) {
    const int b   = blockIdx.x;
    const int tid = threadIdx.x;
    const int nt  = 1024;

    int* R0 = (int*)dyn_smem;
    int* R1 = R0 + NND;
    int* R2 = R1 + NND;
    int* R3 = R2 + NND;
    int* R4 = R3 + NND;   // parent, then depth

    float* S     = (float*)R0;
    float* Z     = (float*)R1;
    float* wsh   = (float*)R2;
    int*   order = R3;
    int*   dep   = R4;

    __shared__ int hist[MAXD + 1];
    __shared__ int lvl_off[MAXD + 2];
    __shared__ int scanbuf[MAXD + 1];
    __shared__ int s_maxLvl;

    const int* tr = tree + (size_t)b * EED * 2;
    const int2* tr2 = (const int2*)tr;

    // ---- build parent[] into R4 ----
    if (tid == 0) { dep[0] = 0; s_maxLvl = 1; }
    for (int e = tid; e < EED; e += nt) {
        int2 st = tr2[e];
        dep[st.y] = st.x;
    }
    __syncthreads();

    // ---- depth via pointer doubling (10 rounds -> depth <= 1024) ----
    int *jA = R0, *jB = R1, *dA = R2, *dB = R3;
    for (int i = tid; i < NND; i += nt) {
        jA[i] = dep[i];              // parent (dep[0]=0)
        dA[i] = (i == 0) ? 0 : 1;
    }
    __syncthreads();
#pragma unroll 1
    for (int r = 0; r < 10; r++) {
        for (int i = tid; i < NND; i += nt) {
            int jj = jA[i];
            dB[i] = dA[i] + dA[jj];
            jB[i] = jA[jj];
        }
        __syncthreads();
        int* tmp;
        tmp = jA; jA = jB; jB = tmp;
        tmp = dA; dA = dB; dB = tmp;
    }
    // final depths are in dA (== R2 after even #swaps); persist into R4
    for (int i = tid; i < NND; i += nt) dep[i] = dA[i];
    __syncthreads();

    // ---- counting sort of edges by child depth ----
    for (int k = tid; k <= MAXD; k += nt) hist[k] = 0;
    __syncthreads();
    for (int e = tid; e < EED; e += nt) {
        int d = dep[tr[2 * e + 1]];
        d = d > MAXD ? MAXD : d;
        atomicAdd(&hist[d], 1);
    }
    __syncthreads();

    // parallel exclusive scan of hist -> lvl_off (Hillis-Steele, 512 bins)
    if (tid <= MAXD) {
        scanbuf[tid] = hist[tid];
        if (hist[tid]) atomicMax(&s_maxLvl, tid);
    }
    __syncthreads();
#pragma unroll 1
    for (int off = 1; off <= MAXD; off <<= 1) {
        int v = 0;
        if (tid <= MAXD && tid >= off) v = scanbuf[tid - off];
        __syncthreads();
        if (tid <= MAXD) scanbuf[tid] += v;
        __syncthreads();
    }
    if (tid <= MAXD) {
        lvl_off[tid + 1] = scanbuf[tid];         // inclusive -> offsets
        hist[tid] = scanbuf[tid] - hist[tid];    // exclusive: scatter cursor
    }
    if (tid == 0) lvl_off[0] = 0;
    __syncthreads();

    for (int e = tid; e < EED; e += nt) {
        int d = dep[tr[2 * e + 1]];
        d = d > MAXD ? MAXD : d;
        int pos = atomicAdd(&hist[d], 1);
        order[pos] = e;
    }
    __syncthreads();

    // ---- init S (feature), Z (ones), w ----
    const float* fb = fin + (size_t)b * NND;
    for (int i = tid; i < NND; i += nt) { S[i] = fb[i]; Z[i] = 1.f; }
    for (int e = tid; e < EED; e += nt) wsh[e] = g_wgt[(size_t)b * EED + e];
    __syncthreads();

    const int maxLvl = s_maxLvl;

    // ---- UP pass: deepest level first; all children of a node share a level
    for (int d = maxLvl; d >= 1; --d) {
        int beg = lvl_off[d], end = lvl_off[d + 1];
        for (int idx = beg + tid; idx < end; idx += nt) {
            int e = order[idx];
            int2 st = tr2[e];
            float we = wsh[e];
            atomicAdd(&S[st.x], we * S[st.y]);
            atomicAdd(&Z[st.x], we * Z[st.y]);
        }
        __syncthreads();
    }

    // ---- DOWN pass: shallowest first; writes to distinct children
    for (int d = 1; d <= maxLvl; ++d) {
        int beg = lvl_off[d], end = lvl_off[d + 1];
        for (int idx = beg + tid; idx < end; idx += nt) {
            int e = order[idx];
            int2 st = tr2[e];
            float we = wsh[e];
            float om = 1.f - we * we;
            S[st.y] = we * S[st.x] + om * S[st.y];
            Z[st.y] = we * Z[st.x] + om * Z[st.y];
        }
        __syncthreads();
    }

    // ---- output = F/G ----
    float* ob = out + (size_t)b * NND;
    for (int i = tid; i < NND; i += nt) ob[i] = S[i] / Z[i];
}

// ---------------------------------------------------------------------------
extern "C" void kernel_launch(void* const* d_in, const int* in_sizes, int n_in,
                              void* d_out, int out_size) {
    const float* f    = (const float*)d_in[0];   // feature_in [8,1,96,96]
    const float* emb  = (const float*)d_in[1];   // embed_in   [8,256,96,96]
    const int*   tree = (const int*)d_in[2];     // tree       [8,9215,2]
    float*       out  = (float*)d_out;           // [8,1,96,96]

    size_t smem_dist = (size_t)TCH * NND * sizeof(float);   // 147456 B
    cudaFuncSetAttribute(dist_kernel,
                         cudaFuncAttributeMaxDynamicSharedMemorySize,
                         (int)smem_dist);
    dist_kernel<<<BS * SPLIT, 1024, smem_dist>>>(emb, tree);

    exp_kernel<<<(BS * EED + 255) / 256, 256>>>();

    size_t smem_scan = 5 * (size_t)NND * sizeof(int);       // 184320 B
    cudaFuncSetAttribute(scan_kernel,
                         cudaFuncAttributeMaxDynamicSharedMemorySize,
                         (int)smem_scan);
    scan_kernel<<<BS, 1024, smem_scan>>>(f, tree, out);
}

// round 4
// speedup vs baseline: 2.0039x; 1.5044x over previous
#include <cuda_runtime.h>
#include <stdint.h>
#include <math.h>

#define BS   8
#define CCH  256
#define NND  9216     // H*W
#define EED  9215     // N-1 edges
#define ZETA 0.01f

#define CPB  16               // channels per dist block
#define GQ   (CCH/CPB)        // 16 groups per batch
#define TCH  2                // channels per tile step
#define NSTEP (CPB/TCH)       // 8 tile steps
#define MAXD 511
#define NT   1024
#define EPT  9                // ceil(EED/NT)

// scratch (static device global — no allocations)
__device__ float g_part[(size_t)BS * GQ * EED];

extern __shared__ float dyn_smem[];

__device__ __forceinline__ void cp_async16(uint32_t saddr, const void* gptr) {
    asm volatile("cp.async.cg.shared.global [%0], [%1], 16;\n"
                 :: "r"(saddr), "l"(gptr));
}
__device__ __forceinline__ void cp_commit() {
    asm volatile("cp.async.commit_group;\n");
}
template <int N>
__device__ __forceinline__ void cp_wait() {
    asm volatile("cp.async.wait_group %0;\n" :: "n"(N));
}

// ---------------------------------------------------------------------------
// K1: partial squared distances. One block per (batch, 16-channel group).
// Double-buffered cp.async tiles of 2 channels (73.7 KB each) overlap the
// global stream with the smem gather compute; per-edge accumulators live in
// registers across the 8 tile steps.
// ---------------------------------------------------------------------------
__global__ void __launch_bounds__(NT, 1)
dist_kernel(const float* __restrict__ emb,
            const int*   __restrict__ tree) {
    float* buf0 = dyn_smem;
    float* buf1 = dyn_smem + TCH * NND;
    const int b   = blockIdx.x / GQ;
    const int g   = blockIdx.x % GQ;
    const int tid = threadIdx.x;

    const float* base = emb + ((size_t)b * CCH + (size_t)g * CPB) * NND;
    uint32_t s0 = (uint32_t)__cvta_generic_to_shared(buf0);
    uint32_t s1 = (uint32_t)__cvta_generic_to_shared(buf1);
    const int WORDS = TCH * NND / 4;   // 4608 16B chunks per tile

    // prefetch tile 0
    for (int i = tid; i < WORDS; i += NT)
        cp_async16(s0 + i * 16, base + i * 4);
    cp_commit();

    // cache this thread's edges in registers
    const int2* tr2 = (const int2*)(tree + (size_t)b * EED * 2);
    int2 ed[EPT];
    float acc[EPT];
#pragma unroll
    for (int k = 0; k < EPT; k++) {
        int e = tid + k * NT;
        ed[k]  = (e < EED) ? tr2[e] : make_int2(0, 0);
        acc[k] = 0.f;
    }

    for (int t = 0; t < NSTEP; t++) {
        if (t + 1 < NSTEP) {
            uint32_t dst = (t & 1) ? s0 : s1;
            const float* srcp = base + (size_t)(t + 1) * TCH * NND;
            for (int i = tid; i < WORDS; i += NT)
                cp_async16(dst + i * 16, srcp + i * 4);
            cp_commit();
            cp_wait<1>();          // tile t complete
        } else {
            cp_wait<0>();
        }
        __syncthreads();
        const float* cur = (t & 1) ? buf1 : buf0;
#pragma unroll
        for (int k = 0; k < EPT; k++) {
            float a0 = cur[ed[k].x];
            float b0 = cur[ed[k].y];
            float a1 = cur[NND + ed[k].x];
            float b1 = cur[NND + ed[k].y];
            float d0 = a0 - b0, d1 = a1 - b1;
            acc[k] += d0 * d0 + d1 * d1;
        }
        __syncthreads();           // all reads done before buffer reuse
    }

    float* outp = g_part + ((size_t)b * GQ + g) * EED;
#pragma unroll
    for (int k = 0; k < EPT; k++) {
        int e = tid + k * NT;
        if (e < EED) outp[e] = acc[k];
    }
}

// ---------------------------------------------------------------------------
// K3: per-batch level-parallel tree scans, all in shared memory.
// smem regions (5 x 36 KB):
//   prologue: R0=parent  R1=depth  R2/R3/R4 = level-sorted (s, t, w)
//   passes:   R0=S       R1=Z      R2/R3/R4 unchanged
// Prologue: depth by direct parent-walk; counting sort by child depth with a
// Hillis-Steele offset scan; edge weight exp folded into the scatter.
// Passes: block-parallel per level for big levels, single-warp for the tail.
// ---------------------------------------------------------------------------
__global__ void __launch_bounds__(NT, 1)
scan_kernel(const float* __restrict__ fin,
            const int*   __restrict__ tree,
            float*       __restrict__ out) {
    const int b   = blockIdx.x;
    const int tid = threadIdx.x;
    const int wid = tid >> 5;
    const int lid = tid & 31;

    int*   R0 = (int*)dyn_smem;
    int*   R1 = R0 + NND;
    int*   R2 = R1 + NND;
    int*   R3 = R2 + NND;
    int*   R4 = R3 + NND;

    int*   par   = R0;
    int*   dep   = R1;
    int*   sSort = R2;
    int*   tSort = R3;
    float* wSort = (float*)R4;
    float* S     = (float*)R0;   // after prologue
    float* Z     = (float*)R1;   // after prologue

    __shared__ int hist[MAXD + 1];
    __shared__ int lvlo[MAXD + 2];
    __shared__ int scanb[MAXD + 1];
    __shared__ int s_maxLvl, s_bad;

    const int2* tr2 = (const int2*)(tree + (size_t)b * EED * 2);

    // ---- parent array ----
    if (tid == 0) { s_maxLvl = 1; s_bad = 0; }
    for (int i = tid; i < NND; i += NT) par[i] = 0;
    __syncthreads();
    for (int e = tid; e < EED; e += NT) {
        int2 st = tr2[e];
        par[st.y] = st.x;
    }
    __syncthreads();

    // ---- depth by direct walk to root ----
    for (int i = tid; i < NND; i += NT) {
        int j = i, d = 0;
        while (j != 0 && d < NND) { j = par[j]; d++; }
        dep[i] = d;
    }
    __syncthreads();

    // ---- histogram of child depths ----
    for (int k = tid; k <= MAXD; k += NT) hist[k] = 0;
    __syncthreads();
    for (int e = tid; e < EED; e += NT) {
        int d = dep[tr2[e].y];
        d = d > MAXD ? MAXD : d;
        atomicAdd(&hist[d], 1);
    }
    __syncthreads();

    // ---- parallel exclusive scan (Hillis-Steele over 512 bins) ----
    if (tid <= MAXD) scanb[tid] = hist[tid];
    __syncthreads();
#pragma unroll 1
    for (int off = 1; off <= MAXD; off <<= 1) {
        int v = 0;
        if (tid <= MAXD && tid >= off) v = scanb[tid - off];
        __syncthreads();
        if (tid <= MAXD) scanb[tid] += v;
        __syncthreads();
    }
    if (tid <= MAXD) {
        lvlo[tid + 1] = scanb[tid];
        hist[tid]     = scanb[tid] - hist[tid];   // scatter cursor (exclusive)
    }
    if (tid == 0) lvlo[0] = 0;
    __syncthreads();
    if (tid <= MAXD) {
        int cnt = lvlo[tid + 1] - lvlo[tid];
        if (cnt > 0)  atomicMax(&s_maxLvl, tid);
        if (cnt > 32) atomicMax(&s_bad, tid);
    }
    __syncthreads();

    // ---- scatter edges into level order, computing weights inline ----
    const float* pp = g_part + (size_t)b * GQ * EED;
    for (int e = tid; e < EED; e += NT) {
        int2 st = tr2[e];
        int d = dep[st.y];
        d = d > MAXD ? MAXD : d;
        float sum = 0.f;
#pragma unroll
        for (int g = 0; g < GQ; g++) sum += pp[(size_t)g * EED + e];
        float w = expf(-ZETA * sum);
        int pos = atomicAdd(&hist[d], 1);
        sSort[pos] = st.x;
        tSort[pos] = st.y;
        wSort[pos] = w;
    }
    __syncthreads();

    // ---- init S (feature), Z (ones); overwrites par/dep ----
    const float* fb = fin + (size_t)b * NND;
    for (int i = tid; i < NND; i += NT) { S[i] = fb[i]; Z[i] = 1.f; }
    __syncthreads();

    const int maxLvl = s_maxLvl;
    const int bad    = s_bad;       // deepest level with count > 32

    // ---- UP pass ----
    // tail (deep, small levels): warp 0 only, syncwarp between levels
    if (wid == 0) {
        for (int d = maxLvl; d > bad; --d) {
            int beg = lvlo[d], end = lvlo[d + 1];
            int idx = beg + lid;
            if (idx < end) {
                float we = wSort[idx];
                int s = sSort[idx], t = tSort[idx];
                atomicAdd(&S[s], we * S[t]);
                atomicAdd(&Z[s], we * Z[t]);
            }
            __syncwarp();
        }
    }
    __syncthreads();
    // big levels: whole block
    for (int d = bad; d >= 1; --d) {
        int beg = lvlo[d], end = lvlo[d + 1];
        for (int idx = beg + tid; idx < end; idx += NT) {
            float we = wSort[idx];
            int s = sSort[idx], t = tSort[idx];
            atomicAdd(&S[s], we * S[t]);
            atomicAdd(&Z[s], we * Z[t]);
        }
        __syncthreads();
    }

    // ---- DOWN pass ----
    for (int d = 1; d <= bad; ++d) {
        int beg = lvlo[d], end = lvlo[d + 1];
        for (int idx = beg + tid; idx < end; idx += NT) {
            float we = wSort[idx];
            float om = 1.f - we * we;
            int s = sSort[idx], t = tSort[idx];
            S[t] = we * S[s] + om * S[t];
            Z[t] = we * Z[s] + om * Z[t];
        }
        __syncthreads();
    }
    if (wid == 0) {
        for (int d = bad + 1; d <= maxLvl; ++d) {
            int beg = lvlo[d], end = lvlo[d + 1];
            int idx = beg + lid;
            if (idx < end) {
                float we = wSort[idx];
                float om = 1.f - we * we;
                int s = sSort[idx], t = tSort[idx];
                S[t] = we * S[s] + om * S[t];
                Z[t] = we * Z[s] + om * Z[t];
            }
            __syncwarp();
        }
    }
    __syncthreads();

    // ---- output = F/G ----
    float* ob = out + (size_t)b * NND;
    for (int i = tid; i < NND; i += NT) ob[i] = S[i] / Z[i];
}

// ---------------------------------------------------------------------------
extern "C" void kernel_launch(void* const* d_in, const int* in_sizes, int n_in,
                              void* d_out, int out_size) {
    const float* f    = (const float*)d_in[0];   // feature_in [8,1,96,96]
    const float* emb  = (const float*)d_in[1];   // embed_in   [8,256,96,96]
    const int*   tree = (const int*)d_in[2];     // tree       [8,9215,2]
    float*       out  = (float*)d_out;           // [8,1,96,96]

    size_t smem_dist = 2 * (size_t)TCH * NND * sizeof(float);   // 147456 B
    cudaFuncSetAttribute(dist_kernel,
                         cudaFuncAttributeMaxDynamicSharedMemorySize,
                         (int)smem_dist);
    dist_kernel<<<BS * GQ, NT, smem_dist>>>(emb, tree);

    size_t smem_scan = 5 * (size_t)NND * sizeof(int);           // 184320 B
    cudaFuncSetAttribute(scan_kernel,
                         cudaFuncAttributeMaxDynamicSharedMemorySize,
                         (int)smem_scan);
    scan_kernel<<<BS, NT, smem_scan>>>(f, tree, out);
}

// round 5
// speedup vs baseline: 2.2908x; 1.1432x over previous
#include <cuda_runtime.h>
#include <stdint.h>
#include <math.h>

#define BS   8
#define CCH  256
#define NND  9216     // H*W
#define EED  9215     // N-1 edges
#define ZETA 0.01f

#define CPB  16               // channels per dist block
#define GQ   (CCH/CPB)        // 16 groups per batch
#define TCH  2                // channels per tile step
#define NSTEP (CPB/TCH)       // 8 tile steps
#define MAXD 511
#define NT   1024
#define EPT  9                // ceil(EED/NT)
#define NCHUNK (NND/NT)       // 9

// scratch (static device globals — no allocations)
__device__ float g_part[(size_t)BS * GQ * EED];
__device__ float g_wgt[(size_t)BS * EED];

extern __shared__ float dyn_smem[];

__device__ __forceinline__ void cp_async16(uint32_t saddr, const void* gptr) {
    asm volatile("cp.async.cg.shared.global [%0], [%1], 16;\n"
                 :: "r"(saddr), "l"(gptr));
}
__device__ __forceinline__ void cp_commit() {
    asm volatile("cp.async.commit_group;\n");
}
template <int N>
__device__ __forceinline__ void cp_wait() {
    asm volatile("cp.async.wait_group %0;\n" :: "n"(N));
}

// ---------------------------------------------------------------------------
// K1: partial squared distances (unchanged — at LTS ceiling).
// ---------------------------------------------------------------------------
__global__ void __launch_bounds__(NT, 1)
dist_kernel(const float* __restrict__ emb,
            const int*   __restrict__ tree) {
    float* buf0 = dyn_smem;
    float* buf1 = dyn_smem + TCH * NND;
    const int b   = blockIdx.x / GQ;
    const int g   = blockIdx.x % GQ;
    const int tid = threadIdx.x;

    const float* base = emb + ((size_t)b * CCH + (size_t)g * CPB) * NND;
    uint32_t s0 = (uint32_t)__cvta_generic_to_shared(buf0);
    uint32_t s1 = (uint32_t)__cvta_generic_to_shared(buf1);
    const int WORDS = TCH * NND / 4;

    for (int i = tid; i < WORDS; i += NT)
        cp_async16(s0 + i * 16, base + i * 4);
    cp_commit();

    const int2* tr2 = (const int2*)(tree + (size_t)b * EED * 2);
    int2 ed[EPT];
    float acc[EPT];
#pragma unroll
    for (int k = 0; k < EPT; k++) {
        int e = tid + k * NT;
        ed[k]  = (e < EED) ? tr2[e] : make_int2(0, 0);
        acc[k] = 0.f;
    }

    for (int t = 0; t < NSTEP; t++) {
        if (t + 1 < NSTEP) {
            uint32_t dst = (t & 1) ? s0 : s1;
            const float* srcp = base + (size_t)(t + 1) * TCH * NND;
            for (int i = tid; i < WORDS; i += NT)
                cp_async16(dst + i * 16, srcp + i * 4);
            cp_commit();
            cp_wait<1>();
        } else {
            cp_wait<0>();
        }
        __syncthreads();
        const float* cur = (t & 1) ? buf1 : buf0;
#pragma unroll
        for (int k = 0; k < EPT; k++) {
            float a0 = cur[ed[k].x];
            float b0 = cur[ed[k].y];
            float a1 = cur[NND + ed[k].x];
            float b1 = cur[NND + ed[k].y];
            float d0 = a0 - b0, d1 = a1 - b1;
            acc[k] += d0 * d0 + d1 * d1;
        }
        __syncthreads();
    }

    float* outp = g_part + ((size_t)b * GQ + g) * EED;
#pragma unroll
    for (int k = 0; k < EPT; k++) {
        int e = tid + k * NT;
        if (e < EED) outp[e] = acc[k];
    }
}

// ---------------------------------------------------------------------------
// K2: reduce partials + exp, grid-wide (off the per-batch critical path)
// ---------------------------------------------------------------------------
__global__ void weight_kernel() {
    int idx = blockIdx.x * blockDim.x + threadIdx.x;
    if (idx >= BS * EED) return;
    int b = idx / EED, e = idx - b * EED;
    const float* pp = g_part + (size_t)b * GQ * EED + e;
    float s = 0.f;
#pragma unroll
    for (int g = 0; g < GQ; g++) s += pp[(size_t)g * EED];
    g_wgt[idx] = __expf(-ZETA * s);
}

// ---------------------------------------------------------------------------
// K3: per-batch level-parallel tree scans.
// smem: region A = par/dep (prologue) -> SZ float2[NND] (passes)   72 KB
//       region B = ST int2[EED] level-sorted edges                 72 KB
//       region C = W  float[EED] level-sorted weights              36 KB
// ---------------------------------------------------------------------------
__global__ void __launch_bounds__(NT, 1)
scan_kernel(const float* __restrict__ fin,
            const int*   __restrict__ tree,
            float*       __restrict__ out) {
    const int b   = blockIdx.x;
    const int tid = threadIdx.x;
    const int wid = tid >> 5;
    const int lid = tid & 31;

    char*   smbase = (char*)dyn_smem;
    float2* SZ = (float2*)smbase;
    int2*   ST = (int2*)(smbase + (size_t)NND * 8);
    float*  W  = (float*)(smbase + (size_t)NND * 8 + (size_t)EED * 8);
    int*    par = (int*)smbase;
    int*    dep = par + NND;

    __shared__ int hist[MAXD + 1];
    __shared__ int lvlo[MAXD + 2];
    __shared__ int warpsum[16];
    __shared__ int s_maxLvl, s_bad;

    const int2* tr2 = (const int2*)(tree + (size_t)b * EED * 2);

    // ---- parent array + per-thread edge cache ----
    if (tid == 0) { s_maxLvl = 1; s_bad = 0; par[0] = 0; dep[0] = 0; }
    int2 ed[EPT];
#pragma unroll
    for (int k = 0; k < EPT; k++) {
        int e = tid + k * NT;
        ed[k] = (e < EED) ? tr2[e] : make_int2(0, 0);
        if (e < EED) par[ed[k].y] = ed[k].x;
    }
    __syncthreads();

    // ---- depth: chunked walk (parent index < child index) ----
#pragma unroll 1
    for (int c = 0; c < NCHUNK; c++) {
        int i = c * NT + tid;
        if (i > 0) {
            int B = c * NT;
            int j = par[i], d = 1;
            while (j >= B && j > 0) { j = par[j]; d++; }
            dep[i] = d + dep[j];
        }
        __syncthreads();
    }

    // ---- histogram of child depths (depths cached in regs) ----
    for (int k = tid; k <= MAXD; k += NT) hist[k] = 0;
    __syncthreads();
    int myd[EPT];
#pragma unroll
    for (int k = 0; k < EPT; k++) {
        int e = tid + k * NT;
        if (e < EED) {
            int d = dep[ed[k].y];
            myd[k] = d > MAXD ? MAXD : d;
            atomicAdd(&hist[myd[k]], 1);
        } else myd[k] = 0;
    }
    __syncthreads();
    // region A (par/dep) dead from here on

    // ---- 2-barrier block scan over 512 bins (warps 0..15) ----
    int binv = 0, incl = 0, bin = 0;
    if (wid < 16) {
        bin  = wid * 32 + lid;
        binv = hist[bin];
        int v = binv;
#pragma unroll
        for (int off = 1; off < 32; off <<= 1) {
            int t = __shfl_up_sync(0xffffffffu, v, off);
            if (lid >= off) v += t;
        }
        if (lid == 31) warpsum[wid] = v;
        incl = v;
    }
    __syncthreads();
    if (wid == 0 && lid < 16) {
        int v = warpsum[lid];
#pragma unroll
        for (int off = 1; off < 16; off <<= 1) {
            int t = __shfl_up_sync(0xffffu, v, off);
            if (lid >= off) v += t;
        }
        warpsum[lid] = v;
    }
    __syncthreads();
    if (wid < 16) {
        incl += wid ? warpsum[wid - 1] : 0;
        lvlo[bin + 1] = incl;
        hist[bin] = incl - binv;          // exclusive cursor for scatter
        if (binv > 0)  atomicMax(&s_maxLvl, bin);
        if (binv > 32) atomicMax(&s_bad, bin);
    }
    if (tid == 0) lvlo[0] = 0;
    __syncthreads();

    // ---- scatter into level order + init SZ (overwrites region A) ----
    const float* wp = g_wgt + (size_t)b * EED;
    const float* fb = fin + (size_t)b * NND;
    for (int i = tid; i < NND; i += NT) SZ[i] = make_float2(fb[i], 1.f);
#pragma unroll
    for (int k = 0; k < EPT; k++) {
        int e = tid + k * NT;
        if (e < EED) {
            float w = wp[e];
            int pos = atomicAdd(&hist[myd[k]], 1);
            ST[pos] = ed[k];
            W[pos]  = w;
        }
    }
    __syncthreads();

    const int maxLvl = s_maxLvl;
    const int bad    = s_bad;        // deepest level with count > 32

    // ---- UP pass: tail (small deep levels) on warp 0 ----
    if (wid == 0) {
#pragma unroll 1
        for (int d = maxLvl; d > bad; --d) {
            int idx = lvlo[d] + lid;
            if (idx < lvlo[d + 1]) {
                int2 st = ST[idx];
                float w = W[idx];
                float2 v = SZ[st.y];
                atomicAdd(&SZ[st.x].x, w * v.x);
                atomicAdd(&SZ[st.x].y, w * v.y);
            }
            __syncwarp();
        }
    }
    __syncthreads();
    // big levels: whole block
#pragma unroll 1
    for (int d = bad; d >= 1; --d) {
        int end = lvlo[d + 1];
        for (int idx = lvlo[d] + tid; idx < end; idx += NT) {
            int2 st = ST[idx];
            float w = W[idx];
            float2 v = SZ[st.y];
            atomicAdd(&SZ[st.x].x, w * v.x);
            atomicAdd(&SZ[st.x].y, w * v.y);
        }
        __syncthreads();
    }

    // ---- DOWN pass ----
#pragma unroll 1
    for (int d = 1; d <= bad; ++d) {
        int end = lvlo[d + 1];
        for (int idx = lvlo[d] + tid; idx < end; idx += NT) {
            int2 st = ST[idx];
            float w = W[idx];
            float om = 1.f - w * w;
            float2 p = SZ[st.x];
            float2 v = SZ[st.y];
            SZ[st.y] = make_float2(w * p.x + om * v.x, w * p.y + om * v.y);
        }
        __syncthreads();
    }
    if (wid == 0) {
#pragma unroll 1
        for (int d = bad + 1; d <= maxLvl; ++d) {
            int idx = lvlo[d] + lid;
            if (idx < lvlo[d + 1]) {
                int2 st = ST[idx];
                float w = W[idx];
                float om = 1.f - w * w;
                float2 p = SZ[st.x];
                float2 v = SZ[st.y];
                SZ[st.y] = make_float2(w * p.x + om * v.x, w * p.y + om * v.y);
            }
            __syncwarp();
        }
    }
    __syncthreads();

    // ---- output = F/G ----
    float* ob = out + (size_t)b * NND;
    for (int i = tid; i < NND; i += NT) {
        float2 v = SZ[i];
        ob[i] = v.x / v.y;
    }
}

// ---------------------------------------------------------------------------
extern "C" void kernel_launch(void* const* d_in, const int* in_sizes, int n_in,
                              void* d_out, int out_size) {
    const float* f    = (const float*)d_in[0];   // feature_in [8,1,96,96]
    const float* emb  = (const float*)d_in[1];   // embed_in   [8,256,96,96]
    const int*   tree = (const int*)d_in[2];     // tree       [8,9215,2]
    float*       out  = (float*)d_out;           // [8,1,96,96]

    size_t smem_dist = 2 * (size_t)TCH * NND * sizeof(float);   // 147456 B
    cudaFuncSetAttribute(dist_kernel,
                         cudaFuncAttributeMaxDynamicSharedMemorySize,
                         (int)smem_dist);
    dist_kernel<<<BS * GQ, NT, smem_dist>>>(emb, tree);

    weight_kernel<<<(BS * EED + 255) / 256, 256>>>();

    size_t smem_scan = (size_t)NND * 8 + (size_t)EED * 8 + (size_t)EED * 4;
    cudaFuncSetAttribute(scan_kernel,
                         cudaFuncAttributeMaxDynamicSharedMemorySize,
                         (int)smem_scan);
    scan_kernel<<<BS, NT, smem_scan>>>(f, tree, out);
}